// round 2
// baseline (speedup 1.0000x reference)
#include <cuda_runtime.h>
#include <math.h>

// Problem constants (shapes fixed by the reference; BS derived at launch).
#define Dg      128     // dim per group
#define Kg      512     // codes per group
#define G       4       // groups
#define E       512     // embedding dim = G*Dg
#define TILE_M  64      // tokens per CTA
#define CHUNK_N 64      // codes per smem chunk
#define THREADS 256

#define XS_STRIDE (TILE_M + 1)    // 65: conflict-free for stride-d access
#define WS_STRIDE (CHUNK_N + 1)   // 65
#define SMEM_BYTES ((Dg * XS_STRIDE + Dg * WS_STRIDE) * (int)sizeof(float))

// Scratch (no allocations allowed).
__device__ float g_wsq[G][Kg];
__device__ float g_loss[G];

// ---------------------------------------------------------------------------
// Init: per-code ||w||^2 and zero the loss accumulators.
// ---------------------------------------------------------------------------
__global__ void vq_init(const float* __restrict__ w0, const float* __restrict__ w1,
                        const float* __restrict__ w2, const float* __restrict__ w3)
{
    const int g = blockIdx.x;
    const float* __restrict__ W = (g == 0) ? w0 : (g == 1) ? w1 : (g == 2) ? w2 : w3;
    const int k = threadIdx.x;
    const float* row = W + (size_t)k * Dg;
    float s = 0.f;
    #pragma unroll 4
    for (int d = 0; d < Dg; ++d) {
        float v = row[d];
        s = fmaf(v, v, s);
    }
    g_wsq[g][k] = s;
    if (k == 0) g_loss[g] = 0.f;
}

// ---------------------------------------------------------------------------
// Main: per (64-token tile, group): streaming distance GEMM + argmin,
// then quantized output + loss partial. Big tiles live in dynamic smem.
// ---------------------------------------------------------------------------
__global__ __launch_bounds__(THREADS) void vq_main(
    const float* __restrict__ lat,
    const float* __restrict__ w0, const float* __restrict__ w1,
    const float* __restrict__ w2, const float* __restrict__ w3,
    float* __restrict__ out, int BS)
{
    extern __shared__ float dsm[];
    float* xs = dsm;                        // [Dg][XS_STRIDE]  ([d][token])
    float* ws = dsm + Dg * XS_STRIDE;       // [Dg][WS_STRIDE]  ([d][code])

    __shared__ float xsq[TILE_M];
    __shared__ int   idxs[TILE_M];
    __shared__ float lred[THREADS / 32];

    const int g = blockIdx.y;
    const float* __restrict__ W = (g == 0) ? w0 : (g == 1) ? w1 : (g == 2) ? w2 : w3;
    const int token0 = blockIdx.x * TILE_M;
    const int tid = threadIdx.x;

    // Load X tile (coalesced gmem; smem transpose conflict-free via stride 65).
    for (int i = tid; i < TILE_M * Dg; i += THREADS) {
        const int t = i >> 7;          // token within tile
        const int d = i & (Dg - 1);    // dim
        xs[d * XS_STRIDE + t] = lat[(size_t)(token0 + t) * E + (size_t)g * Dg + d];
    }
    __syncthreads();

    // Per-token ||x||^2, sequential over d (mimic reference reduce order).
    if (tid < TILE_M) {
        float s = 0.f;
        #pragma unroll 4
        for (int d = 0; d < Dg; ++d) {
            float v = xs[d * XS_STRIDE + tid];
            s = fmaf(v, v, s);
        }
        xsq[tid] = s;
    }
    // xsq visibility guaranteed by the syncs inside the chunk loop below.

    const int row = tid >> 4;   // 0..15 -> 4 tokens each
    const int col = tid & 15;   // 0..15 -> 4 codes each (strided by 16)

    float minv[4] = {INFINITY, INFINITY, INFINITY, INFINITY};
    int   mini[4] = {0, 0, 0, 0};

    for (int c = 0; c < Kg / CHUNK_N; ++c) {
        __syncthreads();  // previous chunk's readers done before overwrite
        for (int i = tid; i < CHUNK_N * Dg; i += THREADS) {
            const int n = i >> 7;
            const int d = i & (Dg - 1);
            ws[d * WS_STRIDE + n] = W[(size_t)(c * CHUNK_N + n) * Dg + d];
        }
        __syncthreads();

        float acc[4][4];
        #pragma unroll
        for (int a = 0; a < 4; ++a)
            #pragma unroll
            for (int b = 0; b < 4; ++b) acc[a][b] = 0.f;

        #pragma unroll 4
        for (int k = 0; k < Dg; ++k) {
            float av[4], bv[4];
            #pragma unroll
            for (int u = 0; u < 4; ++u) av[u] = xs[k * XS_STRIDE + row * 4 + u];  // broadcast
            #pragma unroll
            for (int u = 0; u < 4; ++u) bv[u] = ws[k * WS_STRIDE + col + u * 16]; // 16 banks
            #pragma unroll
            for (int a = 0; a < 4; ++a)
                #pragma unroll
                for (int b = 0; b < 4; ++b)
                    acc[a][b] = fmaf(av[a], bv[b], acc[a][b]);
        }

        // dist = (x_sq + w_sq) - 2*cross  (exact reference formula/order)
        #pragma unroll
        for (int b = 0; b < 4; ++b) {
            const int n = c * CHUNK_N + col + b * 16;
            const float wq = g_wsq[g][n];
            #pragma unroll
            for (int a = 0; a < 4; ++a) {
                const float dist = (xsq[row * 4 + a] + wq) - 2.0f * acc[a][b];
                if (dist < minv[a]) { minv[a] = dist; mini[a] = n; }  // first-idx wins
            }
        }
    }

    // Reduce (min, idx) across the 16 code-columns of each token row.
    #pragma unroll
    for (int off = 8; off >= 1; off >>= 1) {
        #pragma unroll
        for (int a = 0; a < 4; ++a) {
            const float ov = __shfl_xor_sync(0xffffffffu, minv[a], off);
            const int   oi = __shfl_xor_sync(0xffffffffu, mini[a], off);
            if (ov < minv[a] || (ov == minv[a] && oi < mini[a])) {
                minv[a] = ov; mini[a] = oi;
            }
        }
    }
    if (col == 0) {
        #pragma unroll
        for (int a = 0; a < 4; ++a) idxs[row * 4 + a] = mini[a];
    }
    __syncthreads();

    // Epilogue: q_st = x + (q - x), loss partial = sum (q - x)^2.
    float lsum = 0.f;
    for (int i = tid; i < TILE_M * Dg; i += THREADS) {
        const int t = i >> 7;
        const int d = i & (Dg - 1);
        const float x = xs[d * XS_STRIDE + t];
        const float q = W[(size_t)idxs[t] * Dg + d];
        const float diff = q - x;
        out[(size_t)(token0 + t) * E + (size_t)g * Dg + d] = x + diff;
        lsum = fmaf(diff, diff, lsum);
    }

    // Block reduce loss and accumulate per group.
    #pragma unroll
    for (int off = 16; off >= 1; off >>= 1)
        lsum += __shfl_xor_sync(0xffffffffu, lsum, off);
    if ((tid & 31) == 0) lred[tid >> 5] = lsum;
    __syncthreads();
    if (tid < THREADS / 32) {
        float s = lred[tid];
        #pragma unroll
        for (int off = 4; off >= 1; off >>= 1)
            s += __shfl_xor_sync(0x000000ffu, s, off);
        if (tid == 0) atomicAdd(&g_loss[g], s);
    }
}

// ---------------------------------------------------------------------------
// Finalize: vq_loss = sum_g 1.25 * mean_g  -> d_out[out_size-1]
// ---------------------------------------------------------------------------
__global__ void vq_fin(float* __restrict__ out, size_t loss_pos, float inv_count)
{
    float t = 0.f;
    #pragma unroll
    for (int g = 0; g < G; ++g) {
        const float m = g_loss[g] * inv_count;
        t += 1.25f * m;   // BETA*commit + embed with commit == embed numerically
    }
    out[loss_pos] = t;
}

// ---------------------------------------------------------------------------
extern "C" void kernel_launch(void* const* d_in, const int* in_sizes, int n_in,
                              void* d_out, int out_size)
{
    const float* lat = (const float*)d_in[0];
    const float* w1  = (const float*)d_in[1];
    const float* w2  = (const float*)d_in[2];
    const float* w3  = (const float*)d_in[3];
    const float* w4  = (const float*)d_in[4];
    float* out = (float*)d_out;

    const int BS = in_sizes[0] / E;   // 16*2048 = 32768 tokens

    // Allow > 48 KB dynamic smem for vq_main (host-side attr, capture-safe).
    cudaFuncSetAttribute(vq_main, cudaFuncAttributeMaxDynamicSharedMemorySize,
                         SMEM_BYTES);

    vq_init<<<G, Kg>>>(w1, w2, w3, w4);

    dim3 grid(BS / TILE_M, G);
    vq_main<<<grid, THREADS, SMEM_BYTES>>>(lat, w1, w2, w3, w4, out, BS);

    const float inv_count = 1.0f / ((float)BS * (float)Dg);
    vq_fin<<<1, 1>>>(out, (size_t)out_size - 1, inv_count);
}

// round 3
// speedup vs baseline: 1.1199x; 1.1199x over previous
#include <cuda_runtime.h>
#include <math.h>

// Problem constants (shapes fixed by the reference; BS derived at launch).
#define Dg      128     // dim per group
#define Kg      512     // codes per group
#define G       4       // groups
#define E       512     // embedding dim = G*Dg
#define TILE_M  64      // tokens per CTA
#define CHUNK_N 128     // codes per smem chunk
#define THREADS 256

#define XS_STRIDE (TILE_M + 2)    // 66: even (float2-aligned rows), low-conflict
#define WS_STRIDE (CHUNK_N + 2)   // 130
#define SMEM_BYTES ((Dg * XS_STRIDE + Dg * WS_STRIDE) * (int)sizeof(float))

// Scratch (no allocations allowed).
__device__ float g_wsq[G][Kg];
__device__ float g_loss[G];

// ---- f32x2 helpers: two bit-exact fp32 FMAs per instruction (FFMA2) -------
__device__ __forceinline__ unsigned long long ffma2(unsigned long long a,
                                                    unsigned long long b,
                                                    unsigned long long c)
{
    unsigned long long d;
    asm("fma.rn.f32x2 %0, %1, %2, %3;" : "=l"(d) : "l"(a), "l"(b), "l"(c));
    return d;
}
__device__ __forceinline__ unsigned long long pack2(float x)
{
    unsigned long long d;
    unsigned u = __float_as_uint(x);
    asm("mov.b64 %0, {%1, %1};" : "=l"(d) : "r"(u));
    return d;
}
__device__ __forceinline__ float lo2(unsigned long long v) { return __uint_as_float((unsigned)v); }
__device__ __forceinline__ float hi2(unsigned long long v) { return __uint_as_float((unsigned)(v >> 32)); }

// ---------------------------------------------------------------------------
// Init: warp-per-row ||w||^2 (float4 coalesced + shuffle reduce), zero losses.
// grid = G*Kg/8 blocks of 256 threads (8 warps, one code row per warp).
// ---------------------------------------------------------------------------
__global__ void vq_init(const float* __restrict__ w0, const float* __restrict__ w1,
                        const float* __restrict__ w2, const float* __restrict__ w3)
{
    const int gw = blockIdx.x * 8 + (threadIdx.x >> 5);   // global warp = row id
    const int lid = threadIdx.x & 31;
    const int g = gw >> 9;             // row / Kg
    const int k = gw & (Kg - 1);
    const float* __restrict__ W = (g == 0) ? w0 : (g == 1) ? w1 : (g == 2) ? w2 : w3;

    const float4 v = *(const float4*)(W + (size_t)k * Dg + lid * 4);
    float s = v.x * v.x;
    s = fmaf(v.y, v.y, s);
    s = fmaf(v.z, v.z, s);
    s = fmaf(v.w, v.w, s);
    #pragma unroll
    for (int off = 16; off >= 1; off >>= 1)
        s += __shfl_xor_sync(0xffffffffu, s, off);
    if (lid == 0) g_wsq[g][k] = s;
    if (blockIdx.x == 0 && threadIdx.x < G) g_loss[threadIdx.x] = 0.f;
}

// ---------------------------------------------------------------------------
// Main: per (64-token tile, group). Warp = 8-token row group; lane = code col;
// per-thread register tile 8 tokens x 4 codes, packed f32x2 over token pairs.
// ---------------------------------------------------------------------------
__global__ __launch_bounds__(THREADS) void vq_main(
    const float* __restrict__ lat,
    const float* __restrict__ w0, const float* __restrict__ w1,
    const float* __restrict__ w2, const float* __restrict__ w3,
    float* __restrict__ out, int BS)
{
    extern __shared__ float dsm[];
    float* xs = dsm;                        // [Dg][XS_STRIDE]  ([d][token])
    float* ws = dsm + Dg * XS_STRIDE;       // [Dg][WS_STRIDE]  ([d][code])

    __shared__ float xsq[TILE_M];
    __shared__ float swsq[Kg];
    __shared__ int   idxs[TILE_M];
    __shared__ float lred[THREADS / 32];

    const int g = blockIdx.y;
    const float* __restrict__ W = (g == 0) ? w0 : (g == 1) ? w1 : (g == 2) ? w2 : w3;
    const int token0 = blockIdx.x * TILE_M;
    const int tid = threadIdx.x;

    // Load X tile (coalesced gmem; transpose into smem).
    for (int i = tid; i < TILE_M * Dg; i += THREADS) {
        const int t = i >> 7;          // token within tile
        const int d = i & (Dg - 1);    // dim
        xs[d * XS_STRIDE + t] = lat[(size_t)(token0 + t) * E + (size_t)g * Dg + d];
    }
    // Codebook squared norms for this group into smem.
    for (int i = tid; i < Kg; i += THREADS) swsq[i] = g_wsq[g][i];
    __syncthreads();

    // Per-token ||x||^2, sequential over d (same order as the passing R2 run).
    if (tid < TILE_M) {
        float s = 0.f;
        #pragma unroll 4
        for (int d = 0; d < Dg; ++d) {
            float v = xs[d * XS_STRIDE + tid];
            s = fmaf(v, v, s);
        }
        xsq[tid] = s;
    }
    // xsq/swsq visibility covered by the syncs inside the chunk loop.

    const int row = tid >> 5;   // warp id: 8 row groups of 8 tokens
    const int col = tid & 31;   // lane: code columns col + 32u, u=0..3

    float minv[8];
    int   mini[8];
    #pragma unroll
    for (int a = 0; a < 8; ++a) { minv[a] = INFINITY; mini[a] = 0; }

    for (int c = 0; c < Kg / CHUNK_N; ++c) {
        __syncthreads();  // previous chunk's readers done before overwrite
        for (int i = tid; i < CHUNK_N * Dg; i += THREADS) {
            const int n = i >> 7;
            const int d = i & (Dg - 1);
            ws[d * WS_STRIDE + n] = W[(size_t)(c * CHUNK_N + n) * Dg + d];
        }
        __syncthreads();

        unsigned long long acc[4][4];   // [token_pair][code]; each = 2 fp32 accs
        #pragma unroll
        for (int p = 0; p < 4; ++p)
            #pragma unroll
            for (int b = 0; b < 4; ++b) acc[p][b] = 0ull;

        #pragma unroll 4
        for (int k = 0; k < Dg; ++k) {
            const unsigned long long* avp =
                (const unsigned long long*)(xs + k * XS_STRIDE + row * 8);
            unsigned long long av[4];
            #pragma unroll
            for (int p = 0; p < 4; ++p) av[p] = avp[p];          // LDS.64, broadcast
            unsigned long long bvv[4];
            #pragma unroll
            for (int u = 0; u < 4; ++u)
                bvv[u] = pack2(ws[k * WS_STRIDE + col + u * 32]); // conflict-free
            #pragma unroll
            for (int p = 0; p < 4; ++p)
                #pragma unroll
                for (int u = 0; u < 4; ++u)
                    acc[p][u] = ffma2(av[p], bvv[u], acc[p][u]);
        }

        // dist = (x_sq + w_sq) - 2*cross  (identical values to the R2 kernel)
        #pragma unroll
        for (int u = 0; u < 4; ++u) {
            const int n = c * CHUNK_N + col + u * 32;
            const float wq = swsq[n];
            #pragma unroll
            for (int p = 0; p < 4; ++p) {
                const float s0 = xsq[row * 8 + 2 * p]     + wq;
                const float s1 = xsq[row * 8 + 2 * p + 1] + wq;
                const float d0 = fmaf(-2.0f, lo2(acc[p][u]), s0);
                const float d1 = fmaf(-2.0f, hi2(acc[p][u]), s1);
                if (d0 < minv[2 * p])     { minv[2 * p]     = d0; mini[2 * p]     = n; }
                if (d1 < minv[2 * p + 1]) { minv[2 * p + 1] = d1; mini[2 * p + 1] = n; }
            }
        }
    }

    // Reduce (min, idx) across the 32 code-columns of each warp.
    #pragma unroll
    for (int off = 16; off >= 1; off >>= 1) {
        #pragma unroll
        for (int a = 0; a < 8; ++a) {
            const float ov = __shfl_xor_sync(0xffffffffu, minv[a], off);
            const int   oi = __shfl_xor_sync(0xffffffffu, mini[a], off);
            if (ov < minv[a] || (ov == minv[a] && oi < mini[a])) {
                minv[a] = ov; mini[a] = oi;
            }
        }
    }
    if (col == 0) {
        #pragma unroll
        for (int a = 0; a < 8; ++a) idxs[row * 8 + a] = mini[a];
    }
    __syncthreads();

    // Epilogue: q_st = x + (q - x), loss partial = sum (q - x)^2.
    float lsum = 0.f;
    for (int i = tid; i < TILE_M * Dg; i += THREADS) {
        const int t = i >> 7;
        const int d = i & (Dg - 1);
        const float x = xs[d * XS_STRIDE + t];
        const float q = W[(size_t)idxs[t] * Dg + d];
        const float diff = q - x;
        out[(size_t)(token0 + t) * E + (size_t)g * Dg + d] = x + diff;
        lsum = fmaf(diff, diff, lsum);
    }

    // Block reduce loss and accumulate per group.
    #pragma unroll
    for (int off = 16; off >= 1; off >>= 1)
        lsum += __shfl_xor_sync(0xffffffffu, lsum, off);
    if ((tid & 31) == 0) lred[tid >> 5] = lsum;
    __syncthreads();
    if (tid < THREADS / 32) {
        float s = lred[tid];
        #pragma unroll
        for (int off = 4; off >= 1; off >>= 1)
            s += __shfl_xor_sync(0x000000ffu, s, off);
        if (tid == 0) atomicAdd(&g_loss[g], s);
    }
}

// ---------------------------------------------------------------------------
// Finalize: vq_loss = sum_g 1.25 * mean_g  -> d_out[out_size-1]
// ---------------------------------------------------------------------------
__global__ void vq_fin(float* __restrict__ out, size_t loss_pos, float inv_count)
{
    float t = 0.f;
    #pragma unroll
    for (int g = 0; g < G; ++g) {
        const float m = g_loss[g] * inv_count;
        t += 1.25f * m;   // BETA*commit + embed with commit == embed numerically
    }
    out[loss_pos] = t;
}

// ---------------------------------------------------------------------------
extern "C" void kernel_launch(void* const* d_in, const int* in_sizes, int n_in,
                              void* d_out, int out_size)
{
    const float* lat = (const float*)d_in[0];
    const float* w1  = (const float*)d_in[1];
    const float* w2  = (const float*)d_in[2];
    const float* w3  = (const float*)d_in[3];
    const float* w4  = (const float*)d_in[4];
    float* out = (float*)d_out;

    const int BS = in_sizes[0] / E;   // 16*2048 = 32768 tokens

    cudaFuncSetAttribute(vq_main, cudaFuncAttributeMaxDynamicSharedMemorySize,
                         SMEM_BYTES);

    vq_init<<<(G * Kg) / 8, THREADS>>>(w1, w2, w3, w4);

    dim3 grid(BS / TILE_M, G);
    vq_main<<<grid, THREADS, SMEM_BYTES>>>(lat, w1, w2, w3, w4, out, BS);

    const float inv_count = 1.0f / ((float)BS * (float)Dg);
    vq_fin<<<1, 1>>>(out, (size_t)out_size - 1, inv_count);
}